// round 9
// baseline (speedup 1.0000x reference)
#include <cuda_runtime.h>
#include <cuda_fp16.h>
#include <cstdint>

#define NN    8192
#define IND   512
#define OUTD  256
#define BM    64
#define BK    64
#define BN    128
#define SPLITS 2
#define JRANGE (NN / SPLITS)      // 4096
#define NTILES (JRANGE / BK)      // 64
#define LOG2E 1.4426950408889634f

// ---- dynamic smem (bytes) ----
// sP : 2 x (64 rows x 128B swizzled) = 16384 @ 0
// sH : 2 x (64 rows x 256B swizzled) = 32768 @ 16384
// sEr: 3 x 512B                      =  1536 @ 49152
#define SP_OFF   0
#define SP_BUF   8192
#define SH_OFF   16384
#define SH_BUF   16384
#define SER_OFF  49152
#define SMEM_FUSED 50688           // x3 CTAs/SM = 152KB

// XOR swizzle: 16B chunk cb within a row, rotated by row&7
#define SWZ(row, cb) ((((cb) ^ ((row) & 7))) * 16)

// ---------------- scratch ----------------
__device__ __half    g_h16[(size_t)NN * OUTD];            // h fp16 row-major
__device__ float     g_part[(size_t)SPLITS * NN * OUTD];  // split-K partial numerators
__device__ float     g_Lp[SPLITS * NN];                   // split-K partial rowsums
__device__ __align__(16) float2 g_elx[NN];                // (exp(el), exp(.2el)) scaled
__device__ __align__(16) float2 g_erx[NN];                // (exp(er), exp(.2er)) scaled
__device__ float     g_ul[IND];
__device__ float     g_ur[IND];
__device__ float     g_cb[2];

// ---------------- helpers ----------------
__device__ __forceinline__ uint32_t smem_u32(const void* p) {
    return (uint32_t)__cvta_generic_to_shared(p);
}
__device__ __forceinline__ void cp16(void* dst, const void* src) {
    asm volatile("cp.async.cg.shared.global [%0], [%1], 16;" ::
                 "r"(smem_u32(dst)), "l"(src) : "memory");
}
__device__ __forceinline__ void cp_commit() {
    asm volatile("cp.async.commit_group;" ::: "memory");
}
__device__ __forceinline__ void cp_wait0() {
    asm volatile("cp.async.wait_group 0;" ::: "memory");
}
__device__ __forceinline__ float ex2f(float x) {
    float y; asm("ex2.approx.ftz.f32 %0, %1;" : "=f"(y) : "f"(x)); return y;
}
// single-SASS pack of two floats to half2 (F2FP.PACK_AB)
__device__ __forceinline__ uint32_t pack2h(float a, float b) {
    __half2 h = __floats2half2_rn(a, b);
    return *reinterpret_cast<uint32_t*>(&h);
}
__device__ __forceinline__ void ldmA(uint32_t* r, const void* p) {
    uint32_t a = smem_u32(p);
    asm volatile("ldmatrix.sync.aligned.m8n8.x4.shared.b16 {%0,%1,%2,%3}, [%4];"
                 : "=r"(r[0]), "=r"(r[1]), "=r"(r[2]), "=r"(r[3]) : "r"(a));
}
__device__ __forceinline__ void ldmBT(uint32_t* r, const void* p) {
    uint32_t a = smem_u32(p);
    asm volatile("ldmatrix.sync.aligned.m8n8.x4.trans.shared.b16 {%0,%1,%2,%3}, [%4];"
                 : "=r"(r[0]), "=r"(r[1]), "=r"(r[2]), "=r"(r[3]) : "r"(a));
}
__device__ __forceinline__ void mma16816(float* c, const uint32_t* a,
                                         uint32_t b0, uint32_t b1) {
    asm volatile(
        "mma.sync.aligned.m16n8k16.row.col.f32.f16.f16.f32 "
        "{%0,%1,%2,%3},{%4,%5,%6,%7},{%8,%9},{%0,%1,%2,%3};"
        : "+f"(c[0]), "+f"(c[1]), "+f"(c[2]), "+f"(c[3])
        : "r"(a[0]), "r"(a[1]), "r"(a[2]), "r"(a[3]), "r"(b0), "r"(b1));
}

// ---------------- kernel 1: u_l = W @ a_l, u_r = W @ a_r ----------------
__global__ void __launch_bounds__(256) u_kernel(const float* __restrict__ W,
                                                const float* __restrict__ b,
                                                const float* __restrict__ a,
                                                const float* __restrict__ ab) {
    __shared__ float sa[2 * OUTD];
    const int tid = threadIdx.x;
    sa[tid]       = a[tid];
    sa[tid + 256] = a[tid + 256];
    __syncthreads();
    const int lane = tid & 31;
    const int k    = blockIdx.x * 8 + (tid >> 5);
    const float* wr = W + (size_t)k * OUTD + lane * 8;
    float4 v0 = *(const float4*)(wr);
    float4 v1 = *(const float4*)(wr + 4);
    const float* s0 = sa + lane * 8;
    const float* s1 = sa + OUTD + lane * 8;
    float ul = v0.x * s0[0] + v0.y * s0[1] + v0.z * s0[2] + v0.w * s0[3]
             + v1.x * s0[4] + v1.y * s0[5] + v1.z * s0[6] + v1.w * s0[7];
    float ur = v0.x * s1[0] + v0.y * s1[1] + v0.z * s1[2] + v0.w * s1[3]
             + v1.x * s1[4] + v1.y * s1[5] + v1.z * s1[6] + v1.w * s1[7];
    #pragma unroll
    for (int o = 16; o > 0; o >>= 1) {
        ul += __shfl_xor_sync(0xffffffffu, ul, o);
        ur += __shfl_xor_sync(0xffffffffu, ur, o);
    }
    if (lane == 0) { g_ul[k] = ul; g_ur[k] = ur; }
    if (blockIdx.x == 0 && tid == 0) {
        float bl = 0.f, br = 0.f;
        for (int n = 0; n < OUTD; ++n) {
            bl += b[n] * sa[n];
            br += b[n] * sa[OUTD + n];
        }
        g_cb[0] = bl + ab[0];
        g_cb[1] = br;
    }
}

// ---------------- kernel 2: per-node factorized exps of el/er ----------------
__global__ void __launch_bounds__(256) eler_kernel(const float* __restrict__ X) {
    __shared__ float sul[IND], sur[IND];
    const int tid = threadIdx.x;
    sul[tid]       = g_ul[tid];
    sul[tid + 256] = g_ul[tid + 256];
    sur[tid]       = g_ur[tid];
    sur[tid + 256] = g_ur[tid + 256];
    __syncthreads();
    const int lane = tid & 31;
    const int w    = tid >> 5;
    const int i    = blockIdx.x * 8 + w;
    const float* xr = X + (size_t)i * IND;
    float dl = 0.f, dr = 0.f;
    #pragma unroll
    for (int q = 0; q < 4; ++q) {
        int c = q * 128 + lane * 4;
        float4 v = *(const float4*)(xr + c);
        dl += v.x * sul[c] + v.y * sul[c + 1] + v.z * sul[c + 2] + v.w * sul[c + 3];
        dr += v.x * sur[c] + v.y * sur[c + 1] + v.z * sur[c + 2] + v.w * sur[c + 3];
    }
    #pragma unroll
    for (int o = 16; o > 0; o >>= 1) {
        dl += __shfl_xor_sync(0xffffffffu, dl, o);
        dr += __shfl_xor_sync(0xffffffffu, dr, o);
    }
    if (lane == 0) {
        float el = dl + g_cb[0];
        float er = dr + g_cb[1];
        float2 ev, fv;
        ev.x = ex2f(el * LOG2E - 3.0f);
        ev.y = ex2f(el * (0.2f * LOG2E) - 3.0f);
        fv.x = ex2f(er * LOG2E - 3.0f);
        fv.y = ex2f(er * (0.2f * LOG2E) - 3.0f);
        g_elx[i] = ev;
        g_erx[i] = fv;
    }
}

// ---------------- kernel 3: h16 = fp16(X @ W + b), row-major ----------------
__global__ void __launch_bounds__(256, 2) gemm1_kernel(const float* __restrict__ X,
                                                       const float* __restrict__ W,
                                                       const float* __restrict__ b) {
    __shared__ __half sX[128 * 72];
    __shared__ __half sW[64 * 136];
    const int tid  = threadIdx.x;
    const int lane = tid & 31;
    const int wid  = tid >> 5;
    const int mblk = blockIdx.x * 128;
    const int nblk = blockIdx.y * 128;
    const int wm   = (wid >> 1) * 32;
    const int wn   = (wid & 1) * 64;

    float acc[2][8][4];
    #pragma unroll
    for (int i = 0; i < 2; ++i)
        #pragma unroll
        for (int j = 0; j < 8; ++j)
            #pragma unroll
            for (int k = 0; k < 4; ++k) acc[i][j][k] = 0.f;

    for (int k0 = 0; k0 < IND; k0 += 64) {
        __syncthreads();
        #pragma unroll
        for (int pass = 0; pass < 8; ++pass) {
            int row = pass * 16 + (tid >> 4);
            int col = (tid & 15) * 4;
            float4 v = *(const float4*)(X + (size_t)(mblk + row) * IND + k0 + col);
            *(__half2*)&sX[row * 72 + col]     = __floats2half2_rn(v.x, v.y);
            *(__half2*)&sX[row * 72 + col + 2] = __floats2half2_rn(v.z, v.w);
        }
        #pragma unroll
        for (int pass = 0; pass < 8; ++pass) {
            int row = pass * 8 + (tid >> 5);
            int col = (tid & 31) * 4;
            float4 v = *(const float4*)(W + (size_t)(k0 + row) * OUTD + nblk + col);
            *(__half2*)&sW[row * 136 + col]     = __floats2half2_rn(v.x, v.y);
            *(__half2*)&sW[row * 136 + col + 2] = __floats2half2_rn(v.z, v.w);
        }
        __syncthreads();
        #pragma unroll
        for (int kk = 0; kk < 4; ++kk) {
            int kb = kk * 16;
            uint32_t A[2][4];
            #pragma unroll
            for (int mf = 0; mf < 2; ++mf)
                ldmA(A[mf], &sX[(wm + mf * 16 + (lane & 15)) * 72 + kb + (lane >> 4) * 8]);
            #pragma unroll
            for (int nf = 0; nf < 4; ++nf) {
                uint32_t B[4];
                ldmBT(B, &sW[(kb + (lane & 15)) * 136 + wn + nf * 16 + (lane >> 4) * 8]);
                #pragma unroll
                for (int mf = 0; mf < 2; ++mf) {
                    mma16816(acc[mf][2 * nf],     A[mf], B[0], B[1]);
                    mma16816(acc[mf][2 * nf + 1], A[mf], B[2], B[3]);
                }
            }
        }
    }
    #pragma unroll
    for (int mf = 0; mf < 2; ++mf) {
        int grow = mblk + wm + mf * 16 + (lane >> 2);
        #pragma unroll
        for (int nf = 0; nf < 8; ++nf) {
            int gcol = nblk + wn + nf * 8 + (lane & 3) * 2;
            float b0 = b[gcol], b1 = b[gcol + 1];
            *(__half2*)&g_h16[(size_t)grow * OUTD + gcol] =
                __floats2half2_rn(acc[mf][nf][0] + b0, acc[mf][nf][1] + b1);
            *(__half2*)&g_h16[(size_t)(grow + 8) * OUTD + gcol] =
                __floats2half2_rn(acc[mf][nf][2] + b0, acc[mf][nf][3] + b1);
        }
    }
}

// ---------------- kernel 4: fused attention — 64x128 tiles, 3 CTAs/SM ----------
// blockIdx.x: bit0 = N-half, bit1 = split s, rest = row block
__global__ void __launch_bounds__(256, 3) gat_fused_kernel(const int* __restrict__ adj) {
    extern __shared__ __align__(1024) char smem[];

    const int tid  = threadIdx.x;
    const int lane = tid & 31;
    const int wid  = tid >> 5;
    const int nh   = blockIdx.x & 1;
    const int s    = (blockIdx.x >> 1) & 1;
    const int rb   = blockIdx.x >> 2;
    const int i0   = rb * BM;
    const int J0   = s * JRANGE;

    const int r  = tid >> 2;           // 0..63 (P row owned by this thread)
    const int cq = tid & 3;            // col quarter
    const int cg = cq << 4;            // 0,16,32,48
    const int* arow = adj + (size_t)(i0 + r) * NN + J0 + cg;

    const float2 ev = g_elx[i0 + r];

    const int wm = (wid >> 2) * 32;    // MMA row group (0/32)
    const int wn = (wid & 3) * 32;     // MMA col group (0..96 within N-half)

    // ---- prologue: cp {H0, er0, er1}; compute P[0] ----
    #pragma unroll
    for (int p = 0; p < 4; ++p) {
        int idx = p * 256 + tid;
        int row = idx >> 4, cb = idx & 15;
        cp16(smem + SH_OFF + row * 256 + SWZ(row, cb),
             g_h16 + (size_t)(J0 + row) * OUTD + nh * BN + cb * 8);
    }
    if (tid < 32) {
        cp16(smem + SER_OFF + tid * 16,       g_erx + J0 + tid * 2);
        cp16(smem + SER_OFF + 512 + tid * 16, g_erx + J0 + BK + tid * 2);
    }
    cp_commit();
    cp_wait0();
    __syncthreads();

    float psum = 0.f;
    {
        const float4* se = (const float4*)(smem + SER_OFF);
        int4 av_n = __ldcs((const int4*)(arow));
        uint32_t pk[4];
        #pragma unroll
        for (int kk = 0; kk < 4; ++kk) {
            int4 av = av_n;
            if (kk < 3) av_n = __ldcs((const int4*)(arow + 4 * (kk + 1)));
            float4 f0 = se[8 * cq + 2 * kk];
            float4 f1 = se[8 * cq + 2 * kk + 1];
            float p0 = fmaxf(ev.x * f0.x, ev.y * f0.y);
            float p1 = fmaxf(ev.x * f0.z, ev.y * f0.w);
            float p2 = fmaxf(ev.x * f1.x, ev.y * f1.y);
            float p3 = fmaxf(ev.x * f1.z, ev.y * f1.w);
            p0 = (av.x > 0) ? p0 : 0.f;
            p1 = (av.y > 0) ? p1 : 0.f;
            p2 = (av.z > 0) ? p2 : 0.f;
            p3 = (av.w > 0) ? p3 : 0.f;
            if (nh == 0) psum += (p0 + p1) + (p2 + p3);
            pk[2 * (kk & 1)]     = pack2h(p0, p1);
            pk[2 * (kk & 1) + 1] = pack2h(p2, p3);
            if (kk & 1) {
                char* pb = smem + SP_OFF + r * 128;
                *(uint4*)(pb + SWZ(r, 2 * cq + (kk >> 1))) =
                    make_uint4(pk[0], pk[1], pk[2], pk[3]);
            }
        }
    }

    float acc[2][4][4];
    #pragma unroll
    for (int i = 0; i < 2; ++i)
        #pragma unroll
        for (int j = 0; j < 4; ++j)
            #pragma unroll
            for (int k = 0; k < 4; ++k) acc[i][j][k] = 0.f;

    // ---- main loop ----
    for (int t = 0; t < NTILES; ++t) {
        cp_wait0();
        __syncthreads();   // H[t]/er visible; P[t] STS visible; MMA[t-1] done

        const bool more = (t + 1 < NTILES);

        // issue {H[t+1] -> buf (t+1)&1, er[t+2] -> stage (t+2)%3}
        if (more) {
            const int jn = J0 + (t + 1) * BK;
            #pragma unroll
            for (int p = 0; p < 4; ++p) {
                int idx = p * 256 + tid;
                int row = idx >> 4, cb = idx & 15;
                cp16(smem + SH_OFF + ((t + 1) & 1) * SH_BUF + row * 256 + SWZ(row, cb),
                     g_h16 + (size_t)(jn + row) * OUTD + nh * BN + cb * 8);
            }
            if (t + 2 < NTILES && tid < 32)
                cp16(smem + SER_OFF + ((t + 2) % 3) * 512 + tid * 16,
                     g_erx + J0 + (t + 2) * BK + tid * 2);
            cp_commit();
        }

        const char*   sPb = smem + SP_OFF + (t & 1) * SP_BUF;
        const char*   sHb = smem + SH_OFF + (t & 1) * SH_BUF;
        const float4* se  = (const float4*)(smem + SER_OFF + ((t + 1) % 3) * 512);

        int4 av_n;
        if (more) av_n = __ldcs((const int4*)(arow + (t + 1) * BK));

        uint32_t pk[4];

        #pragma unroll
        for (int kk = 0; kk < 4; ++kk) {
            // MMA[t], k-slab kk
            uint32_t A[2][4];
            #pragma unroll
            for (int mf = 0; mf < 2; ++mf) {
                int prow = wm + mf * 16 + (lane & 15);
                ldmA(A[mf], sPb + prow * 128 + SWZ(prow, kk * 2 + (lane >> 4)));
            }
            const int krow = (kk << 4) + (lane & 15);
            const char* hb = sHb + krow * 256;
            #pragma unroll
            for (int nf = 0; nf < 2; ++nf) {
                uint32_t B[4];
                ldmBT(B, hb + SWZ(krow, (wn >> 3) + nf * 2 + (lane >> 4)));
                mma16816(acc[0][2 * nf],     A[0], B[0], B[1]);
                mma16816(acc[0][2 * nf + 1], A[0], B[2], B[3]);
                mma16816(acc[1][2 * nf],     A[1], B[0], B[1]);
                mma16816(acc[1][2 * nf + 1], A[1], B[2], B[3]);
            }

            // P[t+1], quarter kk (overlaps LDSM/HMMA above)
            if (more) {
                int4 av = av_n;
                if (kk < 3) av_n = __ldcs((const int4*)(arow + (t + 1) * BK + 4 * (kk + 1)));
                float4 f0 = se[8 * cq + 2 * kk];
                float4 f1 = se[8 * cq + 2 * kk + 1];
                float p0 = fmaxf(ev.x * f0.x, ev.y * f0.y);
                float p1 = fmaxf(ev.x * f0.z, ev.y * f0.w);
                float p2 = fmaxf(ev.x * f1.x, ev.y * f1.y);
                float p3 = fmaxf(ev.x * f1.z, ev.y * f1.w);
                p0 = (av.x > 0) ? p0 : 0.f;
                p1 = (av.y > 0) ? p1 : 0.f;
                p2 = (av.z > 0) ? p2 : 0.f;
                p3 = (av.w > 0) ? p3 : 0.f;
                if (nh == 0) psum += (p0 + p1) + (p2 + p3);
                pk[2 * (kk & 1)]     = pack2h(p0, p1);
                pk[2 * (kk & 1) + 1] = pack2h(p2, p3);
                if (kk & 1) {
                    char* pb = smem + SP_OFF + ((t + 1) & 1) * SP_BUF + r * 128;
                    *(uint4*)(pb + SWZ(r, 2 * cq + (kk >> 1))) =
                        make_uint4(pk[0], pk[1], pk[2], pk[3]);
                }
            }
        }
    }

    // rowsum: threads 4r..4r+3 are consecutive lanes (valid only for nh==0)
    psum += __shfl_xor_sync(0xffffffffu, psum, 1);
    psum += __shfl_xor_sync(0xffffffffu, psum, 2);
    if (nh == 0 && (tid & 3) == 0) g_Lp[s * NN + i0 + r] = psum;

    // write partial numerators (this CTA's N-half)
    #pragma unroll
    for (int mf = 0; mf < 2; ++mf) {
        int row0 = wm + mf * 16 + (lane >> 2);
        float* d0 = g_part + ((size_t)s * NN + i0 + row0) * OUTD + nh * BN;
        float* d1 = g_part + ((size_t)s * NN + i0 + row0 + 8) * OUTD + nh * BN;
        #pragma unroll
        for (int nf = 0; nf < 4; ++nf) {
            int col = wn + nf * 8 + (lane & 3) * 2;
            *(float2*)(d0 + col) = make_float2(acc[mf][nf][0], acc[mf][nf][1]);
            *(float2*)(d1 + col) = make_float2(acc[mf][nf][2], acc[mf][nf][3]);
        }
    }
}

// ---------------- kernel 5: combine split-K partials ----------------
__global__ void __launch_bounds__(256) combine_kernel(float* __restrict__ out) {
    const int gid = blockIdx.x * 256 + threadIdx.x;
    const int row = gid >> 6;
    const int c   = (gid & 63) * 4;
    const float4 x0 = *(const float4*)(g_part + (size_t)row * OUTD + c);
    const float4 x1 = *(const float4*)(g_part + (size_t)NN * OUTD + (size_t)row * OUTD + c);
    const float inv = 1.0f / (g_Lp[row] + g_Lp[NN + row]);
    float4 o;
    o.x = (x0.x + x1.x) * inv;
    o.y = (x0.y + x1.y) * inv;
    o.z = (x0.z + x1.z) * inv;
    o.w = (x0.w + x1.w) * inv;
    *(float4*)(out + (size_t)row * OUTD + c) = o;
}

// ---------------- launch ----------------
extern "C" void kernel_launch(void* const* d_in, const int* in_sizes, int n_in,
                              void* d_out, int out_size) {
    const int*   adj = (const int*)d_in[0];
    const float* X   = (const float*)d_in[1];
    const float* W   = (const float*)d_in[2];
    const float* b   = (const float*)d_in[3];
    const float* a   = (const float*)d_in[4];
    const float* ab  = (const float*)d_in[5];
    float* out = (float*)d_out;

    cudaFuncSetAttribute(gat_fused_kernel,
                         cudaFuncAttributeMaxDynamicSharedMemorySize, SMEM_FUSED);

    u_kernel<<<64, 256>>>(W, b, a, ab);
    eler_kernel<<<NN / 8, 256>>>(X);
    gemm1_kernel<<<dim3(NN / 128, OUTD / 128), 256>>>(X, W, b);
    gat_fused_kernel<<<(NN / BM) * SPLITS * 2, 256, SMEM_FUSED>>>(adj);
    combine_kernel<<<(NN * OUTD / 4) / 256, 256>>>(out);
}

// round 10
// speedup vs baseline: 2.0775x; 2.0775x over previous
#include <cuda_runtime.h>
#include <cuda_fp16.h>
#include <cstdint>

#define NN    8192
#define IND   512
#define OUTD  256
#define BM    128
#define BK    64
#define NTHR  512
#define SPLITS 2
#define JRANGE (NN / SPLITS)      // 4096
#define NTILES (JRANGE / BK)      // 64
#define LOG2E 1.4426950408889634f

// ---- dynamic smem (bytes) ----
// sP : 2 x (128 rows x 128B swizzled) = 32768 @ 0
// sH : 2 x ( 64 rows x 512B swizzled) = 65536 @ 32768
// sEr: 3 x 512B                       =  1536 @ 98304
#define SP_OFF   0
#define SP_BUF   16384
#define SH_OFF   32768
#define SH_BUF   32768
#define SER_OFF  98304
#define SMEM_FUSED 99840           // 1 CTA/SM (grid 128 <= 148 SMs)

// XOR swizzle: 16B chunk cb within a row, rotated by row&7
#define SWZ(row, cb) ((((cb) ^ ((row) & 7))) * 16)

// ---------------- scratch ----------------
__device__ __half    g_h16[(size_t)NN * OUTD];            // h fp16 row-major
__device__ float     g_part[(size_t)SPLITS * NN * OUTD];  // split-K partial numerators
__device__ float     g_Lp[SPLITS * NN];                   // split-K partial rowsums
__device__ __align__(16) float2 g_elx[NN];                // (exp(el), exp(.2el)) scaled
__device__ __align__(16) float2 g_erx[NN];                // (exp(er), exp(.2er)) scaled
__device__ float     g_ul[IND];
__device__ float     g_ur[IND];
__device__ float     g_cb[2];

// ---------------- helpers ----------------
__device__ __forceinline__ uint32_t smem_u32(const void* p) {
    return (uint32_t)__cvta_generic_to_shared(p);
}
__device__ __forceinline__ void cp16(void* dst, const void* src) {
    asm volatile("cp.async.cg.shared.global [%0], [%1], 16;" ::
                 "r"(smem_u32(dst)), "l"(src) : "memory");
}
__device__ __forceinline__ void cp_commit() {
    asm volatile("cp.async.commit_group;" ::: "memory");
}
__device__ __forceinline__ void cp_wait0() {
    asm volatile("cp.async.wait_group 0;" ::: "memory");
}
__device__ __forceinline__ float ex2f(float x) {
    float y; asm("ex2.approx.ftz.f32 %0, %1;" : "=f"(y) : "f"(x)); return y;
}
// single-SASS pack of two floats to half2 (F2FP.PACK_AB)
__device__ __forceinline__ uint32_t pack2h(float a, float b) {
    __half2 h = __floats2half2_rn(a, b);
    return *reinterpret_cast<uint32_t*>(&h);
}
__device__ __forceinline__ void ldmA(uint32_t* r, const void* p) {
    uint32_t a = smem_u32(p);
    asm volatile("ldmatrix.sync.aligned.m8n8.x4.shared.b16 {%0,%1,%2,%3}, [%4];"
                 : "=r"(r[0]), "=r"(r[1]), "=r"(r[2]), "=r"(r[3]) : "r"(a));
}
__device__ __forceinline__ void ldmBT(uint32_t* r, const void* p) {
    uint32_t a = smem_u32(p);
    asm volatile("ldmatrix.sync.aligned.m8n8.x4.trans.shared.b16 {%0,%1,%2,%3}, [%4];"
                 : "=r"(r[0]), "=r"(r[1]), "=r"(r[2]), "=r"(r[3]) : "r"(a));
}
__device__ __forceinline__ void mma16816(float* c, const uint32_t* a,
                                         uint32_t b0, uint32_t b1) {
    asm volatile(
        "mma.sync.aligned.m16n8k16.row.col.f32.f16.f16.f32 "
        "{%0,%1,%2,%3},{%4,%5,%6,%7},{%8,%9},{%0,%1,%2,%3};"
        : "+f"(c[0]), "+f"(c[1]), "+f"(c[2]), "+f"(c[3])
        : "r"(a[0]), "r"(a[1]), "r"(a[2]), "r"(a[3]), "r"(b0), "r"(b1));
}

// ---------------- kernel 1: u_l = W @ a_l, u_r = W @ a_r ----------------
__global__ void __launch_bounds__(256) u_kernel(const float* __restrict__ W,
                                                const float* __restrict__ b,
                                                const float* __restrict__ a,
                                                const float* __restrict__ ab) {
    __shared__ float sa[2 * OUTD];
    const int tid = threadIdx.x;
    sa[tid]       = a[tid];
    sa[tid + 256] = a[tid + 256];
    __syncthreads();
    const int lane = tid & 31;
    const int k    = blockIdx.x * 8 + (tid >> 5);
    const float* wr = W + (size_t)k * OUTD + lane * 8;
    float4 v0 = *(const float4*)(wr);
    float4 v1 = *(const float4*)(wr + 4);
    const float* s0 = sa + lane * 8;
    const float* s1 = sa + OUTD + lane * 8;
    float ul = v0.x * s0[0] + v0.y * s0[1] + v0.z * s0[2] + v0.w * s0[3]
             + v1.x * s0[4] + v1.y * s0[5] + v1.z * s0[6] + v1.w * s0[7];
    float ur = v0.x * s1[0] + v0.y * s1[1] + v0.z * s1[2] + v0.w * s1[3]
             + v1.x * s1[4] + v1.y * s1[5] + v1.z * s1[6] + v1.w * s1[7];
    #pragma unroll
    for (int o = 16; o > 0; o >>= 1) {
        ul += __shfl_xor_sync(0xffffffffu, ul, o);
        ur += __shfl_xor_sync(0xffffffffu, ur, o);
    }
    if (lane == 0) { g_ul[k] = ul; g_ur[k] = ur; }
    if (blockIdx.x == 0 && tid == 0) {
        float bl = 0.f, br = 0.f;
        for (int n = 0; n < OUTD; ++n) {
            bl += b[n] * sa[n];
            br += b[n] * sa[OUTD + n];
        }
        g_cb[0] = bl + ab[0];
        g_cb[1] = br;
    }
}

// ---------------- kernel 2: per-node factorized exps of el/er ----------------
__global__ void __launch_bounds__(256) eler_kernel(const float* __restrict__ X) {
    __shared__ float sul[IND], sur[IND];
    const int tid = threadIdx.x;
    sul[tid]       = g_ul[tid];
    sul[tid + 256] = g_ul[tid + 256];
    sur[tid]       = g_ur[tid];
    sur[tid + 256] = g_ur[tid + 256];
    __syncthreads();
    const int lane = tid & 31;
    const int w    = tid >> 5;
    const int i    = blockIdx.x * 8 + w;
    const float* xr = X + (size_t)i * IND;
    float dl = 0.f, dr = 0.f;
    #pragma unroll
    for (int q = 0; q < 4; ++q) {
        int c = q * 128 + lane * 4;
        float4 v = *(const float4*)(xr + c);
        dl += v.x * sul[c] + v.y * sul[c + 1] + v.z * sul[c + 2] + v.w * sul[c + 3];
        dr += v.x * sur[c] + v.y * sur[c + 1] + v.z * sur[c + 2] + v.w * sur[c + 3];
    }
    #pragma unroll
    for (int o = 16; o > 0; o >>= 1) {
        dl += __shfl_xor_sync(0xffffffffu, dl, o);
        dr += __shfl_xor_sync(0xffffffffu, dr, o);
    }
    if (lane == 0) {
        float el = dl + g_cb[0];
        float er = dr + g_cb[1];
        float2 ev, fv;
        ev.x = ex2f(el * LOG2E - 3.0f);
        ev.y = ex2f(el * (0.2f * LOG2E) - 3.0f);
        fv.x = ex2f(er * LOG2E - 3.0f);
        fv.y = ex2f(er * (0.2f * LOG2E) - 3.0f);
        g_elx[i] = ev;
        g_erx[i] = fv;
    }
}

// ---------------- kernel 3: h16 = fp16(X @ W + b), row-major ----------------
__global__ void __launch_bounds__(256, 2) gemm1_kernel(const float* __restrict__ X,
                                                       const float* __restrict__ W,
                                                       const float* __restrict__ b) {
    __shared__ __half sX[128 * 72];
    __shared__ __half sW[64 * 136];
    const int tid  = threadIdx.x;
    const int lane = tid & 31;
    const int wid  = tid >> 5;
    const int mblk = blockIdx.x * 128;
    const int nblk = blockIdx.y * 128;
    const int wm   = (wid >> 1) * 32;
    const int wn   = (wid & 1) * 64;

    float acc[2][8][4];
    #pragma unroll
    for (int i = 0; i < 2; ++i)
        #pragma unroll
        for (int j = 0; j < 8; ++j)
            #pragma unroll
            for (int k = 0; k < 4; ++k) acc[i][j][k] = 0.f;

    for (int k0 = 0; k0 < IND; k0 += 64) {
        __syncthreads();
        #pragma unroll
        for (int pass = 0; pass < 8; ++pass) {
            int row = pass * 16 + (tid >> 4);
            int col = (tid & 15) * 4;
            float4 v = *(const float4*)(X + (size_t)(mblk + row) * IND + k0 + col);
            *(__half2*)&sX[row * 72 + col]     = __floats2half2_rn(v.x, v.y);
            *(__half2*)&sX[row * 72 + col + 2] = __floats2half2_rn(v.z, v.w);
        }
        #pragma unroll
        for (int pass = 0; pass < 8; ++pass) {
            int row = pass * 8 + (tid >> 5);
            int col = (tid & 31) * 4;
            float4 v = *(const float4*)(W + (size_t)(k0 + row) * OUTD + nblk + col);
            *(__half2*)&sW[row * 136 + col]     = __floats2half2_rn(v.x, v.y);
            *(__half2*)&sW[row * 136 + col + 2] = __floats2half2_rn(v.z, v.w);
        }
        __syncthreads();
        #pragma unroll
        for (int kk = 0; kk < 4; ++kk) {
            int kb = kk * 16;
            uint32_t A[2][4];
            #pragma unroll
            for (int mf = 0; mf < 2; ++mf)
                ldmA(A[mf], &sX[(wm + mf * 16 + (lane & 15)) * 72 + kb + (lane >> 4) * 8]);
            #pragma unroll
            for (int nf = 0; nf < 4; ++nf) {
                uint32_t B[4];
                ldmBT(B, &sW[(kb + (lane & 15)) * 136 + wn + nf * 16 + (lane >> 4) * 8]);
                #pragma unroll
                for (int mf = 0; mf < 2; ++mf) {
                    mma16816(acc[mf][2 * nf],     A[mf], B[0], B[1]);
                    mma16816(acc[mf][2 * nf + 1], A[mf], B[2], B[3]);
                }
            }
        }
    }
    #pragma unroll
    for (int mf = 0; mf < 2; ++mf) {
        int grow = mblk + wm + mf * 16 + (lane >> 2);
        #pragma unroll
        for (int nf = 0; nf < 8; ++nf) {
            int gcol = nblk + wn + nf * 8 + (lane & 3) * 2;
            float b0 = b[gcol], b1 = b[gcol + 1];
            *(__half2*)&g_h16[(size_t)grow * OUTD + gcol] =
                __floats2half2_rn(acc[mf][nf][0] + b0, acc[mf][nf][1] + b1);
            *(__half2*)&g_h16[(size_t)(grow + 8) * OUTD + gcol] =
                __floats2half2_rn(acc[mf][nf][2] + b0, acc[mf][nf][3] + b1);
        }
    }
}

// ---------------- kernel 4: fused attention — BM=128, 512 thr, 1 CTA/SM --------
// blockIdx.x: bit0 = split s, rest = row block
__global__ void __launch_bounds__(NTHR, 1) gat_fused_kernel(const int* __restrict__ adj) {
    extern __shared__ __align__(1024) char smem[];

    const int tid  = threadIdx.x;
    const int lane = tid & 31;
    const int wid  = tid >> 5;          // 0..15
    const int s    = blockIdx.x & 1;
    const int rb   = blockIdx.x >> 1;
    const int i0   = rb * BM;
    const int J0   = s * JRANGE;

    const int r  = tid >> 2;            // 0..127 (P row owned by this thread)
    const int cq = tid & 3;             // col quarter
    const int cg = cq << 4;             // 0,16,32,48
    const int* arow = adj + (size_t)(i0 + r) * NN + J0 + cg;

    const float2 ev = g_elx[i0 + r];

    const int wm = (wid >> 2) * 32;     // MMA row group (0/32/64/96)
    const int wn = (wid & 3) * 64;      // MMA col group

    // ---- prologue: adj[0] LDG; cp {H0, er0, er1}; compute P[0] ----
    int4 a[4];
    #pragma unroll
    for (int q = 0; q < 4; ++q) a[q] = __ldcs((const int4*)(arow + 4 * q));

    #pragma unroll
    for (int p = 0; p < 4; ++p) {
        int idx = p * NTHR + tid;
        int row = idx >> 5, cb = idx & 31;
        cp16(smem + SH_OFF + row * 512 + SWZ(row, cb),
             g_h16 + (size_t)(J0 + row) * OUTD + cb * 8);
    }
    if (tid < 32) {
        cp16(smem + SER_OFF + tid * 16,       g_erx + J0 + tid * 2);
        cp16(smem + SER_OFF + 512 + tid * 16, g_erx + J0 + BK + tid * 2);
    }
    cp_commit();
    cp_wait0();
    __syncthreads();    // er0 visible to all threads

    float psum = 0.f;
    {
        const float4* se = (const float4*)(smem + SER_OFF);
        uint32_t pk[8];
        #pragma unroll
        for (int kk = 0; kk < 4; ++kk) {
            float4 f0 = se[(cg + 4 * kk) >> 1];
            float4 f1 = se[((cg + 4 * kk) >> 1) + 1];
            int4 av = a[kk];
            float p0 = fmaxf(ev.x * f0.x, ev.y * f0.y);
            float p1 = fmaxf(ev.x * f0.z, ev.y * f0.w);
            float p2 = fmaxf(ev.x * f1.x, ev.y * f1.y);
            float p3 = fmaxf(ev.x * f1.z, ev.y * f1.w);
            p0 = (av.x > 0) ? p0 : 0.f;
            p1 = (av.y > 0) ? p1 : 0.f;
            p2 = (av.z > 0) ? p2 : 0.f;
            p3 = (av.w > 0) ? p3 : 0.f;
            psum += (p0 + p1) + (p2 + p3);
            pk[2 * kk]     = pack2h(p0, p1);
            pk[2 * kk + 1] = pack2h(p2, p3);
        }
        char* pb = smem + SP_OFF + r * 128;
        *(uint4*)(pb + SWZ(r, 2 * cq))     = make_uint4(pk[0], pk[1], pk[2], pk[3]);
        *(uint4*)(pb + SWZ(r, 2 * cq + 1)) = make_uint4(pk[4], pk[5], pk[6], pk[7]);
    }

    float acc[2][8][4];
    #pragma unroll
    for (int i = 0; i < 2; ++i)
        #pragma unroll
        for (int j = 0; j < 8; ++j)
            #pragma unroll
            for (int k = 0; k < 4; ++k) acc[i][j][k] = 0.f;

    // ---- main loop ----
    for (int t = 0; t < NTILES; ++t) {
        cp_wait0();        // {H[t], er[t+1]} landed (group issued at t-1)
        __syncthreads();   // visible to all; P[t] STS visible; MMA[t-1] done

        const bool more = (t + 1 < NTILES);

        // adj[t+1] for P[t+1] (issued a full kk-loop before first use)
        if (more) {
            const int4* an = (const int4*)(arow + (t + 1) * BK);
            #pragma unroll
            for (int q = 0; q < 4; ++q) a[q] = __ldcs(an + q);
        }

        // issue {H[t+1] -> buf (t+1)&1 (freed by MMA[t-1]), er[t+2] -> (t+2)%3}
        if (more) {
            const int jn = J0 + (t + 1) * BK;
            #pragma unroll
            for (int p = 0; p < 4; ++p) {
                int idx = p * NTHR + tid;
                int row = idx >> 5, cb = idx & 31;
                cp16(smem + SH_OFF + ((t + 1) & 1) * SH_BUF + row * 512 + SWZ(row, cb),
                     g_h16 + (size_t)(jn + row) * OUTD + cb * 8);
            }
            if (t + 2 < NTILES && tid < 32)
                cp16(smem + SER_OFF + ((t + 2) % 3) * 512 + tid * 16,
                     g_erx + J0 + (t + 2) * BK + tid * 2);
            cp_commit();
        }

        const char*   sPb = smem + SP_OFF + (t & 1) * SP_BUF;
        const char*   sHb = smem + SH_OFF + (t & 1) * SH_BUF;
        const float4* se  = (const float4*)(smem + SER_OFF + ((t + 1) % 3) * 512);

        uint32_t pk[8];

        #pragma unroll
        for (int kk = 0; kk < 4; ++kk) {
            // MMA[t], k-slab kk
            uint32_t A[2][4];
            #pragma unroll
            for (int mf = 0; mf < 2; ++mf) {
                int prow = wm + mf * 16 + (lane & 15);
                ldmA(A[mf], sPb + prow * 128 + SWZ(prow, kk * 2 + (lane >> 4)));
            }
            const int krow = (kk << 4) + (lane & 15);
            const char* hb = sHb + krow * 512;
            #pragma unroll
            for (int nf = 0; nf < 4; ++nf) {
                uint32_t B[4];
                ldmBT(B, hb + SWZ(krow, (wn >> 3) + nf * 2 + (lane >> 4)));
                mma16816(acc[0][2 * nf],     A[0], B[0], B[1]);
                mma16816(acc[0][2 * nf + 1], A[0], B[2], B[3]);
                mma16816(acc[1][2 * nf],     A[1], B[0], B[1]);
                mma16816(acc[1][2 * nf + 1], A[1], B[2], B[3]);
            }

            // P[t+1], quarter kk (FMA pipe; overlaps LDSM/HMMA above)
            if (more) {
                float4 f0 = se[(cg + 4 * kk) >> 1];
                float4 f1 = se[((cg + 4 * kk) >> 1) + 1];
                int4 av = a[kk];
                float p0 = fmaxf(ev.x * f0.x, ev.y * f0.y);
                float p1 = fmaxf(ev.x * f0.z, ev.y * f0.w);
                float p2 = fmaxf(ev.x * f1.x, ev.y * f1.y);
                float p3 = fmaxf(ev.x * f1.z, ev.y * f1.w);
                p0 = (av.x > 0) ? p0 : 0.f;
                p1 = (av.y > 0) ? p1 : 0.f;
                p2 = (av.z > 0) ? p2 : 0.f;
                p3 = (av.w > 0) ? p3 : 0.f;
                psum += (p0 + p1) + (p2 + p3);
                pk[2 * kk]     = pack2h(p0, p1);
                pk[2 * kk + 1] = pack2h(p2, p3);
            }
        }

        // store P[t+1] into the other sP buffer (read starts after next sync)
        if (more) {
            char* pb = smem + SP_OFF + ((t + 1) & 1) * SP_BUF + r * 128;
            *(uint4*)(pb + SWZ(r, 2 * cq))     = make_uint4(pk[0], pk[1], pk[2], pk[3]);
            *(uint4*)(pb + SWZ(r, 2 * cq + 1)) = make_uint4(pk[4], pk[5], pk[6], pk[7]);
        }
    }

    // rowsum: threads 4r..4r+3 are consecutive lanes
    psum += __shfl_xor_sync(0xffffffffu, psum, 1);
    psum += __shfl_xor_sync(0xffffffffu, psum, 2);
    if ((tid & 3) == 0) g_Lp[s * NN + i0 + r] = psum;

    // write partial numerators
    #pragma unroll
    for (int mf = 0; mf < 2; ++mf) {
        int row0 = wm + mf * 16 + (lane >> 2);
        float* d0 = g_part + ((size_t)s * NN + i0 + row0) * OUTD;
        float* d1 = g_part + ((size_t)s * NN + i0 + row0 + 8) * OUTD;
        #pragma unroll
        for (int nf = 0; nf < 8; ++nf) {
            int col = wn + nf * 8 + (lane & 3) * 2;
            *(float2*)(d0 + col) = make_float2(acc[mf][nf][0], acc[mf][nf][1]);
            *(float2*)(d1 + col) = make_float2(acc[mf][nf][2], acc[mf][nf][3]);
        }
    }
}

// ---------------- kernel 5: combine split-K partials ----------------
__global__ void __launch_bounds__(256) combine_kernel(float* __restrict__ out) {
    const int gid = blockIdx.x * 256 + threadIdx.x;
    const int row = gid >> 6;
    const int c   = (gid & 63) * 4;
    const float4 x0 = *(const float4*)(g_part + (size_t)row * OUTD + c);
    const float4 x1 = *(const float4*)(g_part + (size_t)NN * OUTD + (size_t)row * OUTD + c);
    const float inv = 1.0f / (g_Lp[row] + g_Lp[NN + row]);
    float4 o;
    o.x = (x0.x + x1.x) * inv;
    o.y = (x0.y + x1.y) * inv;
    o.z = (x0.z + x1.z) * inv;
    o.w = (x0.w + x1.w) * inv;
    *(float4*)(out + (size_t)row * OUTD + c) = o;
}

// ---------------- launch ----------------
extern "C" void kernel_launch(void* const* d_in, const int* in_sizes, int n_in,
                              void* d_out, int out_size) {
    const int*   adj = (const int*)d_in[0];
    const float* X   = (const float*)d_in[1];
    const float* W   = (const float*)d_in[2];
    const float* b   = (const float*)d_in[3];
    const float* a   = (const float*)d_in[4];
    const float* ab  = (const float*)d_in[5];
    float* out = (float*)d_out;

    cudaFuncSetAttribute(gat_fused_kernel,
                         cudaFuncAttributeMaxDynamicSharedMemorySize, SMEM_FUSED);

    u_kernel<<<64, 256>>>(W, b, a, ab);
    eler_kernel<<<NN / 8, 256>>>(X);
    gemm1_kernel<<<dim3(NN / 128, OUTD / 128), 256>>>(X, W, b);
    gat_fused_kernel<<<(NN / BM) * SPLITS, NTHR, SMEM_FUSED>>>(adj);
    combine_kernel<<<(NN * OUTD / 4) / 256, 256>>>(out);
}

// round 11
// speedup vs baseline: 2.2212x; 1.0692x over previous
#include <cuda_runtime.h>
#include <cuda_fp16.h>
#include <cstdint>

#define NN    8192
#define IND   512
#define OUTD  256
#define BM    64
#define BK    64
#define SPLITS 2
#define JRANGE (NN / SPLITS)      // 4096
#define NTILES (JRANGE / BK)      // 64
#define LOG2E 1.4426950408889634f

// ---- dynamic smem (bytes) ----
// sP : 2 x (64 rows x 128B swizzled) = 16384 @ 0
// sH : 2 x (64 rows x 512B swizzled) = 65536 @ 16384
// sEr: 3 x 512B                      =  1536 @ 81920
#define SP_OFF   0
#define SP_BUF   8192
#define SH_OFF   16384
#define SH_BUF   32768
#define SER_OFF  81920
#define SMEM_FUSED 83456           // 2 CTAs/SM

// XOR swizzle: 16B chunk cb within a row, rotated by row&7
#define SWZ(row, cb) ((((cb) ^ ((row) & 7))) * 16)

// ---------------- scratch ----------------
__device__ __half    g_h16[(size_t)NN * OUTD];            // h fp16 row-major
__device__ float     g_part[(size_t)SPLITS * NN * OUTD];  // split-K partial numerators
__device__ float     g_Lp[SPLITS * NN];                   // split-K partial rowsums
__device__ __align__(16) float2 g_elx[NN];                // (exp(el), exp(.2el)) scaled
__device__ __align__(16) float2 g_erx[NN];                // (exp(er), exp(.2er)) scaled
__device__ float     g_ul[IND];
__device__ float     g_ur[IND];
__device__ float     g_cb[2];

// ---------------- helpers ----------------
__device__ __forceinline__ uint32_t smem_u32(const void* p) {
    return (uint32_t)__cvta_generic_to_shared(p);
}
__device__ __forceinline__ void cp16(void* dst, const void* src) {
    asm volatile("cp.async.cg.shared.global [%0], [%1], 16;" ::
                 "r"(smem_u32(dst)), "l"(src) : "memory");
}
__device__ __forceinline__ void cp_commit() {
    asm volatile("cp.async.commit_group;" ::: "memory");
}
__device__ __forceinline__ void cp_wait0() {
    asm volatile("cp.async.wait_group 0;" ::: "memory");
}
__device__ __forceinline__ float ex2f(float x) {
    float y; asm("ex2.approx.ftz.f32 %0, %1;" : "=f"(y) : "f"(x)); return y;
}
// single-SASS pack of two floats to half2 (F2FP.PACK_AB)
__device__ __forceinline__ uint32_t pack2h(float a, float b) {
    __half2 h = __floats2half2_rn(a, b);
    return *reinterpret_cast<uint32_t*>(&h);
}
__device__ __forceinline__ void ldmA(uint32_t* r, const void* p) {
    uint32_t a = smem_u32(p);
    asm volatile("ldmatrix.sync.aligned.m8n8.x4.shared.b16 {%0,%1,%2,%3}, [%4];"
                 : "=r"(r[0]), "=r"(r[1]), "=r"(r[2]), "=r"(r[3]) : "r"(a));
}
__device__ __forceinline__ void ldmBT(uint32_t* r, const void* p) {
    uint32_t a = smem_u32(p);
    asm volatile("ldmatrix.sync.aligned.m8n8.x4.trans.shared.b16 {%0,%1,%2,%3}, [%4];"
                 : "=r"(r[0]), "=r"(r[1]), "=r"(r[2]), "=r"(r[3]) : "r"(a));
}
__device__ __forceinline__ void mma16816(float* c, const uint32_t* a,
                                         uint32_t b0, uint32_t b1) {
    asm volatile(
        "mma.sync.aligned.m16n8k16.row.col.f32.f16.f16.f32 "
        "{%0,%1,%2,%3},{%4,%5,%6,%7},{%8,%9},{%0,%1,%2,%3};"
        : "+f"(c[0]), "+f"(c[1]), "+f"(c[2]), "+f"(c[3])
        : "r"(a[0]), "r"(a[1]), "r"(a[2]), "r"(a[3]), "r"(b0), "r"(b1));
}

// ---------------- kernel 1: u_l = W @ a_l, u_r = W @ a_r ----------------
__global__ void __launch_bounds__(256) u_kernel(const float* __restrict__ W,
                                                const float* __restrict__ b,
                                                const float* __restrict__ a,
                                                const float* __restrict__ ab) {
    __shared__ float sa[2 * OUTD];
    const int tid = threadIdx.x;
    sa[tid]       = a[tid];
    sa[tid + 256] = a[tid + 256];
    __syncthreads();
    const int lane = tid & 31;
    const int k    = blockIdx.x * 8 + (tid >> 5);
    const float* wr = W + (size_t)k * OUTD + lane * 8;
    float4 v0 = *(const float4*)(wr);
    float4 v1 = *(const float4*)(wr + 4);
    const float* s0 = sa + lane * 8;
    const float* s1 = sa + OUTD + lane * 8;
    float ul = v0.x * s0[0] + v0.y * s0[1] + v0.z * s0[2] + v0.w * s0[3]
             + v1.x * s0[4] + v1.y * s0[5] + v1.z * s0[6] + v1.w * s0[7];
    float ur = v0.x * s1[0] + v0.y * s1[1] + v0.z * s1[2] + v0.w * s1[3]
             + v1.x * s1[4] + v1.y * s1[5] + v1.z * s1[6] + v1.w * s1[7];
    #pragma unroll
    for (int o = 16; o > 0; o >>= 1) {
        ul += __shfl_xor_sync(0xffffffffu, ul, o);
        ur += __shfl_xor_sync(0xffffffffu, ur, o);
    }
    if (lane == 0) { g_ul[k] = ul; g_ur[k] = ur; }
    if (blockIdx.x == 0 && tid == 0) {
        float bl = 0.f, br = 0.f;
        for (int n = 0; n < OUTD; ++n) {
            bl += b[n] * sa[n];
            br += b[n] * sa[OUTD + n];
        }
        g_cb[0] = bl + ab[0];
        g_cb[1] = br;
    }
}

// ---------------- kernel 2: per-node factorized exps of el/er ----------------
__global__ void __launch_bounds__(256) eler_kernel(const float* __restrict__ X) {
    __shared__ float sul[IND], sur[IND];
    const int tid = threadIdx.x;
    sul[tid]       = g_ul[tid];
    sul[tid + 256] = g_ul[tid + 256];
    sur[tid]       = g_ur[tid];
    sur[tid + 256] = g_ur[tid + 256];
    __syncthreads();
    const int lane = tid & 31;
    const int w    = tid >> 5;
    const int i    = blockIdx.x * 8 + w;
    const float* xr = X + (size_t)i * IND;
    float dl = 0.f, dr = 0.f;
    #pragma unroll
    for (int q = 0; q < 4; ++q) {
        int c = q * 128 + lane * 4;
        float4 v = *(const float4*)(xr + c);
        dl += v.x * sul[c] + v.y * sul[c + 1] + v.z * sul[c + 2] + v.w * sul[c + 3];
        dr += v.x * sur[c] + v.y * sur[c + 1] + v.z * sur[c + 2] + v.w * sur[c + 3];
    }
    #pragma unroll
    for (int o = 16; o > 0; o >>= 1) {
        dl += __shfl_xor_sync(0xffffffffu, dl, o);
        dr += __shfl_xor_sync(0xffffffffu, dr, o);
    }
    if (lane == 0) {
        float el = dl + g_cb[0];
        float er = dr + g_cb[1];
        float2 ev, fv;
        ev.x = ex2f(el * LOG2E - 3.0f);
        ev.y = ex2f(el * (0.2f * LOG2E) - 3.0f);
        fv.x = ex2f(er * LOG2E - 3.0f);
        fv.y = ex2f(er * (0.2f * LOG2E) - 3.0f);
        g_elx[i] = ev;
        g_erx[i] = fv;
    }
}

// ---------------- kernel 3: h16 = fp16(X @ W + b), row-major ----------------
__global__ void __launch_bounds__(256, 2) gemm1_kernel(const float* __restrict__ X,
                                                       const float* __restrict__ W,
                                                       const float* __restrict__ b) {
    __shared__ __half sX[128 * 72];
    __shared__ __half sW[64 * 136];
    const int tid  = threadIdx.x;
    const int lane = tid & 31;
    const int wid  = tid >> 5;
    const int mblk = blockIdx.x * 128;
    const int nblk = blockIdx.y * 128;
    const int wm   = (wid >> 1) * 32;
    const int wn   = (wid & 1) * 64;

    float acc[2][8][4];
    #pragma unroll
    for (int i = 0; i < 2; ++i)
        #pragma unroll
        for (int j = 0; j < 8; ++j)
            #pragma unroll
            for (int k = 0; k < 4; ++k) acc[i][j][k] = 0.f;

    for (int k0 = 0; k0 < IND; k0 += 64) {
        __syncthreads();
        #pragma unroll
        for (int pass = 0; pass < 8; ++pass) {
            int row = pass * 16 + (tid >> 4);
            int col = (tid & 15) * 4;
            float4 v = *(const float4*)(X + (size_t)(mblk + row) * IND + k0 + col);
            *(__half2*)&sX[row * 72 + col]     = __floats2half2_rn(v.x, v.y);
            *(__half2*)&sX[row * 72 + col + 2] = __floats2half2_rn(v.z, v.w);
        }
        #pragma unroll
        for (int pass = 0; pass < 8; ++pass) {
            int row = pass * 8 + (tid >> 5);
            int col = (tid & 31) * 4;
            float4 v = *(const float4*)(W + (size_t)(k0 + row) * OUTD + nblk + col);
            *(__half2*)&sW[row * 136 + col]     = __floats2half2_rn(v.x, v.y);
            *(__half2*)&sW[row * 136 + col + 2] = __floats2half2_rn(v.z, v.w);
        }
        __syncthreads();
        #pragma unroll
        for (int kk = 0; kk < 4; ++kk) {
            int kb = kk * 16;
            uint32_t A[2][4];
            #pragma unroll
            for (int mf = 0; mf < 2; ++mf)
                ldmA(A[mf], &sX[(wm + mf * 16 + (lane & 15)) * 72 + kb + (lane >> 4) * 8]);
            #pragma unroll
            for (int nf = 0; nf < 4; ++nf) {
                uint32_t B[4];
                ldmBT(B, &sW[(kb + (lane & 15)) * 136 + wn + nf * 16 + (lane >> 4) * 8]);
                #pragma unroll
                for (int mf = 0; mf < 2; ++mf) {
                    mma16816(acc[mf][2 * nf],     A[mf], B[0], B[1]);
                    mma16816(acc[mf][2 * nf + 1], A[mf], B[2], B[3]);
                }
            }
        }
    }
    #pragma unroll
    for (int mf = 0; mf < 2; ++mf) {
        int grow = mblk + wm + mf * 16 + (lane >> 2);
        #pragma unroll
        for (int nf = 0; nf < 8; ++nf) {
            int gcol = nblk + wn + nf * 8 + (lane & 3) * 2;
            float b0 = b[gcol], b1 = b[gcol + 1];
            *(__half2*)&g_h16[(size_t)grow * OUTD + gcol] =
                __floats2half2_rn(acc[mf][nf][0] + b0, acc[mf][nf][1] + b1);
            *(__half2*)&g_h16[(size_t)(grow + 8) * OUTD + gcol] =
                __floats2half2_rn(acc[mf][nf][2] + b0, acc[mf][nf][3] + b1);
        }
    }
}

// ---------------- kernel 4: fused attention — R8 structure (best measured) -----
__global__ void __launch_bounds__(256, 2) gat_fused_kernel(const int* __restrict__ adj) {
    extern __shared__ __align__(1024) char smem[];

    const int tid  = threadIdx.x;
    const int lane = tid & 31;
    const int wid  = tid >> 5;
    const int s    = blockIdx.x & 1;
    const int rb   = blockIdx.x >> 1;
    const int i0   = rb * BM;
    const int J0   = s * JRANGE;

    const int r  = tid >> 2;           // 0..63 (P row owned by this thread)
    const int cq = tid & 3;            // col quarter
    const int cg = cq << 4;            // 0,16,32,48
    const int* arow = adj + (size_t)(i0 + r) * NN + J0 + cg;

    const float2 ev = g_elx[i0 + r];

    const int wm = (wid >> 2) * 32;    // MMA row group
    const int wn = (wid & 3) * 64;     // MMA col group

    // ---- prologue: adj[0] LDG; cp {H0, er0, er1}; compute P[0] ----
    int4 a[4];
    #pragma unroll
    for (int q = 0; q < 4; ++q) a[q] = __ldcs((const int4*)(arow + 4 * q));

    #pragma unroll
    for (int p = 0; p < 8; ++p) {
        int idx = p * 256 + tid;
        int row = idx >> 5, cb = idx & 31;
        cp16(smem + SH_OFF + row * 512 + SWZ(row, cb),
             g_h16 + (size_t)(J0 + row) * OUTD + cb * 8);
    }
    if (tid < 32) {
        cp16(smem + SER_OFF + tid * 16,       g_erx + J0 + tid * 2);
        cp16(smem + SER_OFF + 512 + tid * 16, g_erx + J0 + BK + tid * 2);
    }
    cp_commit();
    cp_wait0();
    __syncthreads();    // er0 visible to all threads

    float psum = 0.f;
    {
        const float4* se = (const float4*)(smem + SER_OFF);
        uint32_t pk[8];
        #pragma unroll
        for (int kk = 0; kk < 4; ++kk) {
            float4 f0 = se[(cg + 4 * kk) >> 1];
            float4 f1 = se[((cg + 4 * kk) >> 1) + 1];
            int4 av = a[kk];
            float p0 = fmaxf(ev.x * f0.x, ev.y * f0.y);
            float p1 = fmaxf(ev.x * f0.z, ev.y * f0.w);
            float p2 = fmaxf(ev.x * f1.x, ev.y * f1.y);
            float p3 = fmaxf(ev.x * f1.z, ev.y * f1.w);
            p0 = (av.x > 0) ? p0 : 0.f;
            p1 = (av.y > 0) ? p1 : 0.f;
            p2 = (av.z > 0) ? p2 : 0.f;
            p3 = (av.w > 0) ? p3 : 0.f;
            psum += (p0 + p1) + (p2 + p3);
            pk[2 * kk]     = pack2h(p0, p1);
            pk[2 * kk + 1] = pack2h(p2, p3);
        }
        char* pb = smem + SP_OFF + r * 128;
        *(uint4*)(pb + SWZ(r, 2 * cq))     = make_uint4(pk[0], pk[1], pk[2], pk[3]);
        *(uint4*)(pb + SWZ(r, 2 * cq + 1)) = make_uint4(pk[4], pk[5], pk[6], pk[7]);
    }

    float acc[2][8][4];
    #pragma unroll
    for (int i = 0; i < 2; ++i)
        #pragma unroll
        for (int j = 0; j < 8; ++j)
            #pragma unroll
            for (int k = 0; k < 4; ++k) acc[i][j][k] = 0.f;

    // ---- main loop ----
    for (int t = 0; t < NTILES; ++t) {
        cp_wait0();        // {H[t], er[t+1]} landed (group issued at t-1)
        __syncthreads();   // visible to all; P[t] STS visible; MMA[t-1] done

        const bool more = (t + 1 < NTILES);

        // issue {H[t+1] -> buf (t+1)&1 (freed by MMA[t-1]), er[t+2] -> (t+2)%3}
        // issued FIRST after the sync to maximize cp.async slack
        if (more) {
            const int jn = J0 + (t + 1) * BK;
            #pragma unroll
            for (int p = 0; p < 8; ++p) {
                int idx = p * 256 + tid;
                int row = idx >> 5, cb = idx & 31;
                cp16(smem + SH_OFF + ((t + 1) & 1) * SH_BUF + row * 512 + SWZ(row, cb),
                     g_h16 + (size_t)(jn + row) * OUTD + cb * 8);
            }
            if (t + 2 < NTILES && tid < 32)
                cp16(smem + SER_OFF + ((t + 2) % 3) * 512 + tid * 16,
                     g_erx + J0 + (t + 2) * BK + tid * 2);
            cp_commit();
        }

        // adj[t+1] for P[t+1] (consumed late in kk loop -> latency hidden)
        if (more) {
            const int4* an = (const int4*)(arow + (t + 1) * BK);
            #pragma unroll
            for (int q = 0; q < 4; ++q) a[q] = __ldcs(an + q);
        }

        const char*   sPb = smem + SP_OFF + (t & 1) * SP_BUF;
        const char*   sHb = smem + SH_OFF + (t & 1) * SH_BUF;
        const float4* se  = (const float4*)(smem + SER_OFF + ((t + 1) % 3) * 512);

        uint32_t pk[8];

        #pragma unroll
        for (int kk = 0; kk < 4; ++kk) {
            // MMA[t], k-slab kk
            uint32_t A[2][4];
            #pragma unroll
            for (int mf = 0; mf < 2; ++mf) {
                int prow = wm + mf * 16 + (lane & 15);
                ldmA(A[mf], sPb + prow * 128 + SWZ(prow, kk * 2 + (lane >> 4)));
            }
            const int krow = (kk << 4) + (lane & 15);
            const char* hb = sHb + krow * 512;
            #pragma unroll
            for (int nf = 0; nf < 4; ++nf) {
                uint32_t B[4];
                ldmBT(B, hb + SWZ(krow, (wn >> 3) + nf * 2 + (lane >> 4)));
                mma16816(acc[0][2 * nf],     A[0], B[0], B[1]);
                mma16816(acc[0][2 * nf + 1], A[0], B[2], B[3]);
                mma16816(acc[1][2 * nf],     A[1], B[0], B[1]);
                mma16816(acc[1][2 * nf + 1], A[1], B[2], B[3]);
            }

            // P[t+1], quarter kk (FMA pipe; overlaps LDSM/HMMA above)
            if (more) {
                float4 f0 = se[(cg + 4 * kk) >> 1];
                float4 f1 = se[((cg + 4 * kk) >> 1) + 1];
                int4 av = a[kk];
                float p0 = fmaxf(ev.x * f0.x, ev.y * f0.y);
                float p1 = fmaxf(ev.x * f0.z, ev.y * f0.w);
                float p2 = fmaxf(ev.x * f1.x, ev.y * f1.y);
                float p3 = fmaxf(ev.x * f1.z, ev.y * f1.w);
                p0 = (av.x > 0) ? p0 : 0.f;
                p1 = (av.y > 0) ? p1 : 0.f;
                p2 = (av.z > 0) ? p2 : 0.f;
                p3 = (av.w > 0) ? p3 : 0.f;
                psum += (p0 + p1) + (p2 + p3);
                pk[2 * kk]     = pack2h(p0, p1);
                pk[2 * kk + 1] = pack2h(p2, p3);
            }
        }

        // store P[t+1] into the other sP buffer (read starts after next sync)
        if (more) {
            char* pb = smem + SP_OFF + ((t + 1) & 1) * SP_BUF + r * 128;
            *(uint4*)(pb + SWZ(r, 2 * cq))     = make_uint4(pk[0], pk[1], pk[2], pk[3]);
            *(uint4*)(pb + SWZ(r, 2 * cq + 1)) = make_uint4(pk[4], pk[5], pk[6], pk[7]);
        }
    }

    // rowsum: threads 4r..4r+3 are consecutive lanes
    psum += __shfl_xor_sync(0xffffffffu, psum, 1);
    psum += __shfl_xor_sync(0xffffffffu, psum, 2);
    if ((tid & 3) == 0) g_Lp[s * NN + i0 + r] = psum;

    // write partial numerators
    #pragma unroll
    for (int mf = 0; mf < 2; ++mf) {
        int row0 = wm + mf * 16 + (lane >> 2);
        float* d0 = g_part + ((size_t)s * NN + i0 + row0) * OUTD;
        float* d1 = g_part + ((size_t)s * NN + i0 + row0 + 8) * OUTD;
        #pragma unroll
        for (int nf = 0; nf < 8; ++nf) {
            int col = wn + nf * 8 + (lane & 3) * 2;
            *(float2*)(d0 + col) = make_float2(acc[mf][nf][0], acc[mf][nf][1]);
            *(float2*)(d1 + col) = make_float2(acc[mf][nf][2], acc[mf][nf][3]);
        }
    }
}

// ---------------- kernel 5: combine split-K partials ----------------
__global__ void __launch_bounds__(256) combine_kernel(float* __restrict__ out) {
    const int gid = blockIdx.x * 256 + threadIdx.x;
    const int row = gid >> 6;
    const int c   = (gid & 63) * 4;
    const float4 x0 = *(const float4*)(g_part + (size_t)row * OUTD + c);
    const float4 x1 = *(const float4*)(g_part + (size_t)NN * OUTD + (size_t)row * OUTD + c);
    const float inv = 1.0f / (g_Lp[row] + g_Lp[NN + row]);
    float4 o;
    o.x = (x0.x + x1.x) * inv;
    o.y = (x0.y + x1.y) * inv;
    o.z = (x0.z + x1.z) * inv;
    o.w = (x0.w + x1.w) * inv;
    *(float4*)(out + (size_t)row * OUTD + c) = o;
}

// ---------------- launch ----------------
extern "C" void kernel_launch(void* const* d_in, const int* in_sizes, int n_in,
                              void* d_out, int out_size) {
    const int*   adj = (const int*)d_in[0];
    const float* X   = (const float*)d_in[1];
    const float* W   = (const float*)d_in[2];
    const float* b   = (const float*)d_in[3];
    const float* a   = (const float*)d_in[4];
    const float* ab  = (const float*)d_in[5];
    float* out = (float*)d_out;

    cudaFuncSetAttribute(gat_fused_kernel,
                         cudaFuncAttributeMaxDynamicSharedMemorySize, SMEM_FUSED);

    u_kernel<<<64, 256>>>(W, b, a, ab);
    eler_kernel<<<NN / 8, 256>>>(X);
    gemm1_kernel<<<dim3(NN / 128, OUTD / 128), 256>>>(X, W, b);
    gat_fused_kernel<<<(NN / BM) * SPLITS, 256, SMEM_FUSED>>>(adj);
    combine_kernel<<<(NN * OUTD / 4) / 256, 256>>>(out);
}

// round 12
// speedup vs baseline: 2.2555x; 1.0154x over previous
#include <cuda_runtime.h>
#include <cuda_fp16.h>
#include <cstdint>

#define NN    8192
#define IND   512
#define OUTD  256
#define BM    64
#define BK    64
#define SPLITS 2
#define JRANGE (NN / SPLITS)      // 4096
#define NTILES (JRANGE / BK)      // 64
#define LOG2E 1.4426950408889634f

// ---- fused kernel dynamic smem (bytes) ----
#define SP_OFF   0
#define SP_BUF   8192
#define SH_OFF   16384
#define SH_BUF   32768
#define SER_OFF  81920
#define SMEM_FUSED 83456           // 2 CTAs/SM

// XOR swizzle: 16B chunk cb within a row, rotated by row&7
#define SWZ(row, cb) ((((cb) ^ ((row) & 7))) * 16)

// ---------------- scratch ----------------
__device__ __half    g_h16[(size_t)NN * OUTD];            // h fp16 row-major
__device__ __half    g_xh[(size_t)NN * IND];              // X fp16 (written by eler)
__device__ __half    g_wh[(size_t)IND * OUTD];            // W fp16 (written by u)
__device__ float     g_part[(size_t)SPLITS * NN * OUTD];  // split-K partial numerators
__device__ float     g_Lp[SPLITS * NN];                   // split-K partial rowsums
__device__ __align__(16) float2 g_elx[NN];                // (exp(el), exp(.2el)) scaled
__device__ __align__(16) float2 g_erx[NN];                // (exp(er), exp(.2er)) scaled
__device__ float     g_ul[IND];
__device__ float     g_ur[IND];
__device__ float     g_cb[2];

// ---------------- helpers ----------------
__device__ __forceinline__ uint32_t smem_u32(const void* p) {
    return (uint32_t)__cvta_generic_to_shared(p);
}
__device__ __forceinline__ void cp16(void* dst, const void* src) {
    asm volatile("cp.async.cg.shared.global [%0], [%1], 16;" ::
                 "r"(smem_u32(dst)), "l"(src) : "memory");
}
__device__ __forceinline__ void cp_commit() {
    asm volatile("cp.async.commit_group;" ::: "memory");
}
__device__ __forceinline__ void cp_wait0() {
    asm volatile("cp.async.wait_group 0;" ::: "memory");
}
__device__ __forceinline__ float ex2f(float x) {
    float y; asm("ex2.approx.ftz.f32 %0, %1;" : "=f"(y) : "f"(x)); return y;
}
// single-SASS pack of two floats to half2 (F2FP.PACK_AB)
__device__ __forceinline__ uint32_t pack2h(float a, float b) {
    __half2 h = __floats2half2_rn(a, b);
    return *reinterpret_cast<uint32_t*>(&h);
}
__device__ __forceinline__ void ldmA(uint32_t* r, const void* p) {
    uint32_t a = smem_u32(p);
    asm volatile("ldmatrix.sync.aligned.m8n8.x4.shared.b16 {%0,%1,%2,%3}, [%4];"
                 : "=r"(r[0]), "=r"(r[1]), "=r"(r[2]), "=r"(r[3]) : "r"(a));
}
__device__ __forceinline__ void ldmBT(uint32_t* r, const void* p) {
    uint32_t a = smem_u32(p);
    asm volatile("ldmatrix.sync.aligned.m8n8.x4.trans.shared.b16 {%0,%1,%2,%3}, [%4];"
                 : "=r"(r[0]), "=r"(r[1]), "=r"(r[2]), "=r"(r[3]) : "r"(a));
}
__device__ __forceinline__ void mma16816(float* c, const uint32_t* a,
                                         uint32_t b0, uint32_t b1) {
    asm volatile(
        "mma.sync.aligned.m16n8k16.row.col.f32.f16.f16.f32 "
        "{%0,%1,%2,%3},{%4,%5,%6,%7},{%8,%9},{%0,%1,%2,%3};"
        : "+f"(c[0]), "+f"(c[1]), "+f"(c[2]), "+f"(c[3])
        : "r"(a[0]), "r"(a[1]), "r"(a[2]), "r"(a[3]), "r"(b0), "r"(b1));
}

// ---------------- kernel 1: u vectors + W -> fp16 ----------------
__global__ void __launch_bounds__(256) u_kernel(const float* __restrict__ W,
                                                const float* __restrict__ b,
                                                const float* __restrict__ a,
                                                const float* __restrict__ ab) {
    __shared__ float sa[2 * OUTD];
    const int tid = threadIdx.x;
    sa[tid]       = a[tid];
    sa[tid + 256] = a[tid + 256];
    __syncthreads();
    const int lane = tid & 31;
    const int k    = blockIdx.x * 8 + (tid >> 5);
    const float* wr = W + (size_t)k * OUTD + lane * 8;
    float4 v0 = *(const float4*)(wr);
    float4 v1 = *(const float4*)(wr + 4);
    // write W as fp16 (for gemm1 v2)
    {
        uint4 wq;
        wq.x = pack2h(v0.x, v0.y);
        wq.y = pack2h(v0.z, v0.w);
        wq.z = pack2h(v1.x, v1.y);
        wq.w = pack2h(v1.z, v1.w);
        *(uint4*)(g_wh + (size_t)k * OUTD + lane * 8) = wq;
    }
    const float* s0 = sa + lane * 8;
    const float* s1 = sa + OUTD + lane * 8;
    float ul = v0.x * s0[0] + v0.y * s0[1] + v0.z * s0[2] + v0.w * s0[3]
             + v1.x * s0[4] + v1.y * s0[5] + v1.z * s0[6] + v1.w * s0[7];
    float ur = v0.x * s1[0] + v0.y * s1[1] + v0.z * s1[2] + v0.w * s1[3]
             + v1.x * s1[4] + v1.y * s1[5] + v1.z * s1[6] + v1.w * s1[7];
    #pragma unroll
    for (int o = 16; o > 0; o >>= 1) {
        ul += __shfl_xor_sync(0xffffffffu, ul, o);
        ur += __shfl_xor_sync(0xffffffffu, ur, o);
    }
    if (lane == 0) { g_ul[k] = ul; g_ur[k] = ur; }
    if (blockIdx.x == 0 && tid == 0) {
        float bl = 0.f, br = 0.f;
        for (int n = 0; n < OUTD; ++n) {
            bl += b[n] * sa[n];
            br += b[n] * sa[OUTD + n];
        }
        g_cb[0] = bl + ab[0];
        g_cb[1] = br;
    }
}

// ---------------- kernel 2: el/er exps + X -> fp16 ----------------
__global__ void __launch_bounds__(256) eler_kernel(const float* __restrict__ X) {
    __shared__ float sul[IND], sur[IND];
    const int tid = threadIdx.x;
    sul[tid]       = g_ul[tid];
    sul[tid + 256] = g_ul[tid + 256];
    sur[tid]       = g_ur[tid];
    sur[tid + 256] = g_ur[tid + 256];
    __syncthreads();
    const int lane = tid & 31;
    const int w    = tid >> 5;
    const int i    = blockIdx.x * 8 + w;
    const float* xr = X + (size_t)i * IND;
    float dl = 0.f, dr = 0.f;
    #pragma unroll
    for (int q = 0; q < 4; ++q) {
        int c = q * 128 + lane * 4;
        float4 v = *(const float4*)(xr + c);
        // write X as fp16 (for gemm1 v2)
        uint2 xq;
        xq.x = pack2h(v.x, v.y);
        xq.y = pack2h(v.z, v.w);
        *(uint2*)(g_xh + (size_t)i * IND + c) = xq;
        dl += v.x * sul[c] + v.y * sul[c + 1] + v.z * sul[c + 2] + v.w * sul[c + 3];
        dr += v.x * sur[c] + v.y * sur[c + 1] + v.z * sur[c + 2] + v.w * sur[c + 3];
    }
    #pragma unroll
    for (int o = 16; o > 0; o >>= 1) {
        dl += __shfl_xor_sync(0xffffffffu, dl, o);
        dr += __shfl_xor_sync(0xffffffffu, dr, o);
    }
    if (lane == 0) {
        float el = dl + g_cb[0];
        float er = dr + g_cb[1];
        float2 ev, fv;
        ev.x = ex2f(el * LOG2E - 3.0f);
        ev.y = ex2f(el * (0.2f * LOG2E) - 3.0f);
        fv.x = ex2f(er * LOG2E - 3.0f);
        fv.y = ex2f(er * (0.2f * LOG2E) - 3.0f);
        g_elx[i] = ev;
        g_erx[i] = fv;
    }
}

// ---------------- kernel 3: gemm1 v2 — fp16 operands, cp.async pipeline --------
// h16 = fp16(Xh @ Wh + b); grid (NN/128, OUTD/128)
// smem: sX 2 x (128 rows x 128B swz) = 32768 @0 ; sW 2 x (64 rows x 256B swz) @32768
#define G1_SMEM 65536
__global__ void __launch_bounds__(256, 2) gemm1_kernel(const float* __restrict__ b) {
    extern __shared__ __align__(1024) char smem[];
    char* sX = smem;
    char* sW = smem + 32768;

    const int tid  = threadIdx.x;
    const int lane = tid & 31;
    const int wid  = tid >> 5;
    const int mblk = blockIdx.x * 128;
    const int nblk = blockIdx.y * 128;
    const int wm   = (wid >> 1) * 32;
    const int wn   = (wid & 1) * 64;

    float acc[2][8][4];
    #pragma unroll
    for (int i = 0; i < 2; ++i)
        #pragma unroll
        for (int j = 0; j < 8; ++j)
            #pragma unroll
            for (int k = 0; k < 4; ++k) acc[i][j][k] = 0.f;

    // prologue: stage k0=0
    #pragma unroll
    for (int p = 0; p < 4; ++p) {
        int idx = p * 256 + tid;
        int row = idx >> 3, cb = idx & 7;
        cp16(sX + row * 128 + SWZ(row, cb),
             g_xh + (size_t)(mblk + row) * IND + cb * 8);
    }
    #pragma unroll
    for (int p = 0; p < 4; ++p) {
        int idx = p * 256 + tid;
        int row = idx >> 4, cb = idx & 15;
        cp16(sW + row * 256 + SWZ(row, cb),
             g_wh + (size_t)row * OUTD + nblk + cb * 8);
    }
    cp_commit();

    for (int ki = 0; ki < IND / 64; ++ki) {
        cp_wait0();
        __syncthreads();   // stage ki ready; MMA ki-1 done -> other buf free

        if (ki + 1 < IND / 64) {
            const int k0 = (ki + 1) * 64;
            const int nb = (ki + 1) & 1;
            #pragma unroll
            for (int p = 0; p < 4; ++p) {
                int idx = p * 256 + tid;
                int row = idx >> 3, cb = idx & 7;
                cp16(sX + nb * 16384 + row * 128 + SWZ(row, cb),
                     g_xh + (size_t)(mblk + row) * IND + k0 + cb * 8);
            }
            #pragma unroll
            for (int p = 0; p < 4; ++p) {
                int idx = p * 256 + tid;
                int row = idx >> 4, cb = idx & 15;
                cp16(sW + nb * 16384 + row * 256 + SWZ(row, cb),
                     g_wh + (size_t)(k0 + row) * OUTD + nblk + cb * 8);
            }
            cp_commit();
        }

        const char* sXb = sX + (ki & 1) * 16384;
        const char* sWb = sW + (ki & 1) * 16384;
        #pragma unroll
        for (int kk = 0; kk < 4; ++kk) {
            uint32_t A[2][4];
            #pragma unroll
            for (int mf = 0; mf < 2; ++mf) {
                int prow = wm + mf * 16 + (lane & 15);
                ldmA(A[mf], sXb + prow * 128 + SWZ(prow, kk * 2 + (lane >> 4)));
            }
            const int krow = (kk << 4) + (lane & 15);
            const char* wb = sWb + krow * 256;
            #pragma unroll
            for (int nf = 0; nf < 4; ++nf) {
                uint32_t B[4];
                ldmBT(B, wb + SWZ(krow, (wn >> 3) + nf * 2 + (lane >> 4)));
                #pragma unroll
                for (int mf = 0; mf < 2; ++mf) {
                    mma16816(acc[mf][2 * nf],     A[mf], B[0], B[1]);
                    mma16816(acc[mf][2 * nf + 1], A[mf], B[2], B[3]);
                }
            }
        }
    }

    #pragma unroll
    for (int mf = 0; mf < 2; ++mf) {
        int grow = mblk + wm + mf * 16 + (lane >> 2);
        #pragma unroll
        for (int nf = 0; nf < 8; ++nf) {
            int gcol = nblk + wn + nf * 8 + (lane & 3) * 2;
            float b0 = b[gcol], b1 = b[gcol + 1];
            *(__half2*)&g_h16[(size_t)grow * OUTD + gcol] =
                __floats2half2_rn(acc[mf][nf][0] + b0, acc[mf][nf][1] + b1);
            *(__half2*)&g_h16[(size_t)(grow + 8) * OUTD + gcol] =
                __floats2half2_rn(acc[mf][nf][2] + b0, acc[mf][nf][3] + b1);
        }
    }
}

// ---------------- kernel 4: fused attention — R11 verbatim (best measured) -----
__global__ void __launch_bounds__(256, 2) gat_fused_kernel(const int* __restrict__ adj) {
    extern __shared__ __align__(1024) char smem[];

    const int tid  = threadIdx.x;
    const int lane = tid & 31;
    const int wid  = tid >> 5;
    const int s    = blockIdx.x & 1;
    const int rb   = blockIdx.x >> 1;
    const int i0   = rb * BM;
    const int J0   = s * JRANGE;

    const int r  = tid >> 2;
    const int cq = tid & 3;
    const int cg = cq << 4;
    const int* arow = adj + (size_t)(i0 + r) * NN + J0 + cg;

    const float2 ev = g_elx[i0 + r];

    const int wm = (wid >> 2) * 32;
    const int wn = (wid & 3) * 64;

    int4 a[4];
    #pragma unroll
    for (int q = 0; q < 4; ++q) a[q] = __ldcs((const int4*)(arow + 4 * q));

    #pragma unroll
    for (int p = 0; p < 8; ++p) {
        int idx = p * 256 + tid;
        int row = idx >> 5, cb = idx & 31;
        cp16(smem + SH_OFF + row * 512 + SWZ(row, cb),
             g_h16 + (size_t)(J0 + row) * OUTD + cb * 8);
    }
    if (tid < 32) {
        cp16(smem + SER_OFF + tid * 16,       g_erx + J0 + tid * 2);
        cp16(smem + SER_OFF + 512 + tid * 16, g_erx + J0 + BK + tid * 2);
    }
    cp_commit();
    cp_wait0();
    __syncthreads();

    float psum = 0.f;
    {
        const float4* se = (const float4*)(smem + SER_OFF);
        uint32_t pk[8];
        #pragma unroll
        for (int kk = 0; kk < 4; ++kk) {
            float4 f0 = se[(cg + 4 * kk) >> 1];
            float4 f1 = se[((cg + 4 * kk) >> 1) + 1];
            int4 av = a[kk];
            float p0 = fmaxf(ev.x * f0.x, ev.y * f0.y);
            float p1 = fmaxf(ev.x * f0.z, ev.y * f0.w);
            float p2 = fmaxf(ev.x * f1.x, ev.y * f1.y);
            float p3 = fmaxf(ev.x * f1.z, ev.y * f1.w);
            p0 = (av.x > 0) ? p0 : 0.f;
            p1 = (av.y > 0) ? p1 : 0.f;
            p2 = (av.z > 0) ? p2 : 0.f;
            p3 = (av.w > 0) ? p3 : 0.f;
            psum += (p0 + p1) + (p2 + p3);
            pk[2 * kk]     = pack2h(p0, p1);
            pk[2 * kk + 1] = pack2h(p2, p3);
        }
        char* pb = smem + SP_OFF + r * 128;
        *(uint4*)(pb + SWZ(r, 2 * cq))     = make_uint4(pk[0], pk[1], pk[2], pk[3]);
        *(uint4*)(pb + SWZ(r, 2 * cq + 1)) = make_uint4(pk[4], pk[5], pk[6], pk[7]);
    }

    float acc[2][8][4];
    #pragma unroll
    for (int i = 0; i < 2; ++i)
        #pragma unroll
        for (int j = 0; j < 8; ++j)
            #pragma unroll
            for (int k = 0; k < 4; ++k) acc[i][j][k] = 0.f;

    for (int t = 0; t < NTILES; ++t) {
        cp_wait0();
        __syncthreads();

        const bool more = (t + 1 < NTILES);

        if (more) {
            const int jn = J0 + (t + 1) * BK;
            #pragma unroll
            for (int p = 0; p < 8; ++p) {
                int idx = p * 256 + tid;
                int row = idx >> 5, cb = idx & 31;
                cp16(smem + SH_OFF + ((t + 1) & 1) * SH_BUF + row * 512 + SWZ(row, cb),
                     g_h16 + (size_t)(jn + row) * OUTD + cb * 8);
            }
            if (t + 2 < NTILES && tid < 32)
                cp16(smem + SER_OFF + ((t + 2) % 3) * 512 + tid * 16,
                     g_erx + J0 + (t + 2) * BK + tid * 2);
            cp_commit();
        }

        if (more) {
            const int4* an = (const int4*)(arow + (t + 1) * BK);
            #pragma unroll
            for (int q = 0; q < 4; ++q) a[q] = __ldcs(an + q);
        }

        const char*   sPb = smem + SP_OFF + (t & 1) * SP_BUF;
        const char*   sHb = smem + SH_OFF + (t & 1) * SH_BUF;
        const float4* se  = (const float4*)(smem + SER_OFF + ((t + 1) % 3) * 512);

        uint32_t pk[8];

        #pragma unroll
        for (int kk = 0; kk < 4; ++kk) {
            uint32_t A[2][4];
            #pragma unroll
            for (int mf = 0; mf < 2; ++mf) {
                int prow = wm + mf * 16 + (lane & 15);
                ldmA(A[mf], sPb + prow * 128 + SWZ(prow, kk * 2 + (lane >> 4)));
            }
            const int krow = (kk << 4) + (lane & 15);
            const char* hb = sHb + krow * 512;
            #pragma unroll
            for (int nf = 0; nf < 4; ++nf) {
                uint32_t B[4];
                ldmBT(B, hb + SWZ(krow, (wn >> 3) + nf * 2 + (lane >> 4)));
                mma16816(acc[0][2 * nf],     A[0], B[0], B[1]);
                mma16816(acc[0][2 * nf + 1], A[0], B[2], B[3]);
                mma16816(acc[1][2 * nf],     A[1], B[0], B[1]);
                mma16816(acc[1][2 * nf + 1], A[1], B[2], B[3]);
            }

            if (more) {
                float4 f0 = se[(cg + 4 * kk) >> 1];
                float4 f1 = se[((cg + 4 * kk) >> 1) + 1];
                int4 av = a[kk];
                float p0 = fmaxf(ev.x * f0.x, ev.y * f0.y);
                float p1 = fmaxf(ev.x * f0.z, ev.y * f0.w);
                float p2 = fmaxf(ev.x * f1.x, ev.y * f1.y);
                float p3 = fmaxf(ev.x * f1.z, ev.y * f1.w);
                p0 = (av.x > 0) ? p0 : 0.f;
                p1 = (av.y > 0) ? p1 : 0.f;
                p2 = (av.z > 0) ? p2 : 0.f;
                p3 = (av.w > 0) ? p3 : 0.f;
                psum += (p0 + p1) + (p2 + p3);
                pk[2 * kk]     = pack2h(p0, p1);
                pk[2 * kk + 1] = pack2h(p2, p3);
            }
        }

        if (more) {
            char* pb = smem + SP_OFF + ((t + 1) & 1) * SP_BUF + r * 128;
            *(uint4*)(pb + SWZ(r, 2 * cq))     = make_uint4(pk[0], pk[1], pk[2], pk[3]);
            *(uint4*)(pb + SWZ(r, 2 * cq + 1)) = make_uint4(pk[4], pk[5], pk[6], pk[7]);
        }
    }

    psum += __shfl_xor_sync(0xffffffffu, psum, 1);
    psum += __shfl_xor_sync(0xffffffffu, psum, 2);
    if ((tid & 3) == 0) g_Lp[s * NN + i0 + r] = psum;

    #pragma unroll
    for (int mf = 0; mf < 2; ++mf) {
        int row0 = wm + mf * 16 + (lane >> 2);
        float* d0 = g_part + ((size_t)s * NN + i0 + row0) * OUTD;
        float* d1 = g_part + ((size_t)s * NN + i0 + row0 + 8) * OUTD;
        #pragma unroll
        for (int nf = 0; nf < 8; ++nf) {
            int col = wn + nf * 8 + (lane & 3) * 2;
            *(float2*)(d0 + col) = make_float2(acc[mf][nf][0], acc[mf][nf][1]);
            *(float2*)(d1 + col) = make_float2(acc[mf][nf][2], acc[mf][nf][3]);
        }
    }
}

// ---------------- kernel 5: combine split-K partials ----------------
__global__ void __launch_bounds__(256) combine_kernel(float* __restrict__ out) {
    const int gid = blockIdx.x * 256 + threadIdx.x;
    const int row = gid >> 6;
    const int c   = (gid & 63) * 4;
    const float4 x0 = __ldcs((const float4*)(g_part + (size_t)row * OUTD + c));
    const float4 x1 = __ldcs((const float4*)(g_part + (size_t)NN * OUTD + (size_t)row * OUTD + c));
    const float inv = 1.0f / (g_Lp[row] + g_Lp[NN + row]);
    float4 o;
    o.x = (x0.x + x1.x) * inv;
    o.y = (x0.y + x1.y) * inv;
    o.z = (x0.z + x1.z) * inv;
    o.w = (x0.w + x1.w) * inv;
    *(float4*)(out + (size_t)row * OUTD + c) = o;
}

// ---------------- launch ----------------
extern "C" void kernel_launch(void* const* d_in, const int* in_sizes, int n_in,
                              void* d_out, int out_size) {
    const int*   adj = (const int*)d_in[0];
    const float* X   = (const float*)d_in[1];
    const float* W   = (const float*)d_in[2];
    const float* b   = (const float*)d_in[3];
    const float* a   = (const float*)d_in[4];
    const float* ab  = (const float*)d_in[5];
    float* out = (float*)d_out;

    cudaFuncSetAttribute(gat_fused_kernel,
                         cudaFuncAttributeMaxDynamicSharedMemorySize, SMEM_FUSED);
    cudaFuncSetAttribute(gemm1_kernel,
                         cudaFuncAttributeMaxDynamicSharedMemorySize, G1_SMEM);

    u_kernel<<<64, 256>>>(W, b, a, ab);
    eler_kernel<<<NN / 8, 256>>>(X);
    gemm1_kernel<<<dim3(NN / 128, OUTD / 128), 256, G1_SMEM>>>(b);
    gat_fused_kernel<<<(NN / BM) * SPLITS, 256, SMEM_FUSED>>>(adj);
    combine_kernel<<<(NN * OUTD / 4) / 256, 256>>>(out);
}